// round 15
// baseline (speedup 1.0000x reference)
#include <cuda_runtime.h>
#include <cuda_fp16.h>
#include <cstdint>

#define DIM    64
#define CODES  512
#define NTOK   262144
#define TPB    256
#define TILTOK 128
#define NTILE  (NTOK / TILTOK)   // 2048
#define GRID2  304               // 2 CTAs per SM (152 SMs)
#define FLTMAX 3.402823466e38f

// Output layout (float32, concatenated tuple)
#define OFF_Q    0L
#define OFF_QL   16777216L
#define OFF_IDX  16777217L
#define OFF_CL   17039361L
#define OFF_EMB  17039362L
#define OFF_N    17072130L
#define OFF_M    17072642L

// vq_mma smem byte offsets (total 102400 -> 2 CTAs/SM)
#define SMB_A    0          // A permuted fp16: 32KB
#define SMB_B    32768      // B half-resident: 64KB
#define SMB_N2   98304      // this half's norms: 256 f
#define SMB_RB   99328      // best per (token,cg): 256 f
#define SMB_RB2  100352     // 2nd best: 256 f
#define SMB_RI   101376     // idx: 256 i
#define SMEM_BYTES 102400

__device__ float  g_embT[CODES * DIM];   // [c][d] fp32 (gather + rescan)
__device__ uint4  g_bperm[8192];         // packed fp16-split B fragments (hi,hi,lo,lo)
__device__ float  g_norm[CODES];
__device__ int    g_maxbits;             // max code norm (float bits, positives)
__device__ float  g_ni[CODES];
__device__ float  g_eofxT[CODES * DIM];  // [c][d]
__device__ float  g_loss;
__device__ int    g_idx[NTOK];
__device__ float  g_hb1[2 * NTOK];       // per-half best
__device__ float  g_hb2[2 * NTOK];       // per-half 2nd best
__device__ int    g_hix[2 * NTOK];       // per-half argmin (global code)

// ---------------- helpers ----------------
__device__ __forceinline__ void red_f(float* p, float v) {
    asm volatile("red.global.add.f32 [%0], %1;" :: "l"(p), "f"(v) : "memory");
}
__device__ __forceinline__ void red_v2(float* p, float a, float b) {
    asm volatile("red.global.add.v2.f32 [%0], {%1, %2};" :: "l"(p), "f"(a), "f"(b) : "memory");
}
__device__ __forceinline__ void mma_f16(float* d, const uint4 a, uint32_t b0, uint32_t b1) {
    asm("mma.sync.aligned.m16n8k16.row.col.f32.f16.f16.f32 "
        "{%0,%1,%2,%3}, {%4,%5,%6,%7}, {%8,%9}, {%0,%1,%2,%3};"
        : "+f"(d[0]), "+f"(d[1]), "+f"(d[2]), "+f"(d[3])
        : "r"(a.x), "r"(a.y), "r"(a.z), "r"(a.w), "r"(b0), "r"(b1));
}
__device__ __forceinline__ uint32_t smem_u32(const void* p) {
    uint32_t a;
    asm("{ .reg .u64 t; cvta.to.shared.u64 t, %1; cvt.u32.u64 %0, t; }" : "=r"(a) : "l"(p));
    return a;
}
__device__ __forceinline__ void cp16(uint32_t dst, const void* src) {
    asm volatile("cp.async.cg.shared.global [%0], [%1], 16;" :: "r"(dst), "l"(src) : "memory");
}
#define CP_COMMIT() asm volatile("cp.async.commit_group;" ::: "memory")
#define CP_WAIT0()  asm volatile("cp.async.wait_group 0;" ::: "memory")

__device__ __forceinline__ void split1(float v, __half& h, __half& l) {
    h = __float2half_rn(v);
    l = __float2half_rn(v - __half2float(h));
}

// ---------------- k1: zero + norms + maxnorm + transpose + packed fp16-split B ----------------
__global__ void vq_split(const float* __restrict__ emb) {
    const int idx = blockIdx.x * 512 + threadIdx.x;   // 0..32767

    g_eofxT[idx] = 0.f;
    if (idx < CODES) g_ni[idx] = 0.f;
    if (idx == 0) g_loss = 0.f;

    { int c = idx >> 6, d = idx & 63; g_embT[idx] = emb[d * CODES + c]; }

    if (idx < CODES) {
        float s = 0.f;
        #pragma unroll
        for (int d = 0; d < DIM; d++) {
            float v = emb[d * CODES + idx];
            s = fmaf(v, v, s);
        }
        g_norm[idx] = s;
        atomicMax(&g_maxbits, __float_as_int(s));   // positives: int order == float order
    }

    // B fragment slots: idx = (cfrag*4 + ks)*32 + lane, cfrag = code>>3
    if (idx < 8192) {
        int l  = idx & 31;
        int ks = (idx >> 5) & 3;
        int cf = idx >> 7;
        int n  = cf * 8 + (l >> 2);
        int k0 = ks * 16 + 2 * (l & 3);
        float v00 = emb[k0 * CODES + n];
        float v01 = emb[(k0 + 1) * CODES + n];
        float v10 = emb[(k0 + 8) * CODES + n];
        float v11 = emb[(k0 + 9) * CODES + n];
        __half h00, l00, h01, l01, h10, l10, h11, l11;
        split1(v00, h00, l00); split1(v01, h01, l01);
        split1(v10, h10, l10); split1(v11, h11, l11);
        uint4 o;
        { __half2 t = __halves2half2(h00, h01); o.x = *reinterpret_cast<uint32_t*>(&t); }
        { __half2 t = __halves2half2(h10, h11); o.y = *reinterpret_cast<uint32_t*>(&t); }
        { __half2 t = __halves2half2(l00, l01); o.z = *reinterpret_cast<uint32_t*>(&t); }
        { __half2 t = __halves2half2(l10, l11); o.w = *reinterpret_cast<uint32_t*>(&t); }
        g_bperm[idx] = o;
    }
}

// ---------------- k2: persistent fp16 3-term MMA, half codebook per CTA ----------------
extern __shared__ char sm[];

__global__ void __launch_bounds__(TPB, 2)
vq_mma(const float* __restrict__ x) {
    const int tid  = threadIdx.x;
    const int lane = tid & 31, wid = tid >> 5;
    const int tg = wid & 3;          // token group (32 tokens)
    const int cg = wid >> 2;         // code group (128 of this CTA's 256 codes)
    const int g  = lane >> 2;
    const int tig = lane & 3;
    const int half = blockIdx.x & 1;      // code half (constant per CTA)
    const int cbase = half * 256;

    float* sN   = (float*)(sm + SMB_N2);
    float* sRb  = (float*)(sm + SMB_RB);
    float* sRb2 = (float*)(sm + SMB_RB2);
    int*   sRi  = (int*)(sm + SMB_RI);
    const uint32_t smbase = smem_u32(sm);

    // ---- one-time: this half's norms + resident half-B (64KB) ----
    sN[tid] = g_norm[cbase + tid];
    {
        const char* src = (const char*)(g_bperm + half * 4096);
        #pragma unroll
        for (int i = 0; i < 16; i++) {
            int off = (i * TPB + tid) * 16;
            cp16(smbase + SMB_B + off, src + off);
        }
        CP_COMMIT();
        CP_WAIT0();
    }
    __syncthreads();

    for (int tile = blockIdx.x >> 1; tile < NTILE; tile += GRID2 / 2) {
        const int gtok0 = tile * TILTOK;

        // ---- load x (half token per thread), write permuted A (fp16 split) ----
        {
            const int T = tid >> 1, hx = tid & 1;
            const float4* xg = (const float4*)(x + (size_t)(gtok0 + T) * DIM + hx * 32);
            #pragma unroll
            for (int j = 0; j < 8; j++) {
                float4 v = xg[j];
                #pragma unroll
                for (int pp = 0; pp < 2; pp++) {
                    int k = hx * 32 + 4 * j + 2 * pp;
                    float a = pp ? v.z : v.x;
                    float b = pp ? v.w : v.y;
                    int ks = k >> 4, kk = k & 15;
                    int sel8 = kk >> 3, ktig = (kk & 7) >> 1;
                    int areg = sel8 * 2 + ((T >> 3) & 1);
                    __half ha, la, hb, lb;
                    split1(a, ha, la); split1(b, hb, lb);
                    int slot = ((T >> 4) * 4 + ks) * 2;
                    uint32_t byte = (uint32_t)slot * 512 + (uint32_t)((T & 7) * 4) * 16
                                  + (uint32_t)ktig * 16 + (uint32_t)areg * 4;
                    __half2 hh = __halves2half2(ha, hb);
                    __half2 ll = __halves2half2(la, lb);
                    *(uint32_t*)(sm + SMB_A + byte)       = *reinterpret_cast<uint32_t*>(&hh);
                    *(uint32_t*)(sm + SMB_A + byte + 512) = *reinterpret_cast<uint32_t*>(&ll);
                }
            }
        }
        __syncthreads();

        // ---- mainloop: warp covers 32 tokens x 128 codes, 4 chunks of 32 codes ----
        float best[4], bsec[4]; int bidx[4];
        #pragma unroll
        for (int s = 0; s < 4; s++) { best[s] = FLTMAX; bsec[s] = FLTMAX; bidx[s] = 0; }

        #pragma unroll
        for (int ch = 0; ch < 4; ch++) {
            float acc[2][4][4];
            #pragma unroll
            for (int mf = 0; mf < 2; mf++)
                #pragma unroll
                for (int j = 0; j < 4; j++)
                    #pragma unroll
                    for (int q = 0; q < 4; q++) acc[mf][j][q] = 0.f;

            #pragma unroll
            for (int ks = 0; ks < 4; ks++) {
                uint4 af[2][2];
                #pragma unroll
                for (int mf = 0; mf < 2; mf++)
                    #pragma unroll
                    for (int hl = 0; hl < 2; hl++)
                        af[mf][hl] = *(const uint4*)(sm + SMB_A +
                            (((tg * 2 + mf) * 4 + ks) * 2 + hl) * 512 + lane * 16);
                uint4 bf[4];
                #pragma unroll
                for (int j = 0; j < 4; j++)
                    bf[j] = *(const uint4*)(sm + SMB_B +
                        ((cg * 16 + ch * 4 + j) * 4 + ks) * 512 + lane * 16);
                #pragma unroll
                for (int mf = 0; mf < 2; mf++) {
                    #pragma unroll
                    for (int j = 0; j < 4; j++) {
                        mma_f16(acc[mf][j], af[mf][0], bf[j].x, bf[j].y);  // xh·eh
                        mma_f16(acc[mf][j], af[mf][0], bf[j].z, bf[j].w);  // xh·el
                        mma_f16(acc[mf][j], af[mf][1], bf[j].x, bf[j].y);  // xl·eh
                    }
                }
            }
            // epilogue chunk: dist + top-2 (codes ascending)
            #pragma unroll
            for (int j = 0; j < 4; j++) {
                int cl = cg * 128 + (ch * 4 + j) * 8 + 2 * tig;   // local code
                float n0 = sN[cl], n1 = sN[cl + 1];
                #pragma unroll
                for (int mf = 0; mf < 2; mf++) {
                    float dv[4];
                    dv[0] = fmaf(-2.f, acc[mf][j][0], n0);
                    dv[1] = fmaf(-2.f, acc[mf][j][1], n1);
                    dv[2] = fmaf(-2.f, acc[mf][j][2], n0);
                    dv[3] = fmaf(-2.f, acc[mf][j][3], n1);
                    #pragma unroll
                    for (int q = 0; q < 4; q++) {
                        int s = mf * 2 + (q >> 1);
                        int c = cbase + cl + (q & 1);
                        if (dv[q] < best[s]) { bsec[s] = best[s]; best[s] = dv[q]; bidx[s] = c; }
                        else if (dv[q] < bsec[s]) bsec[s] = dv[q];
                    }
                }
            }
        }

        // merge across tig lanes (same tokens)
        #pragma unroll
        for (int off = 1; off <= 2; off <<= 1) {
            #pragma unroll
            for (int s = 0; s < 4; s++) {
                float ob  = __shfl_xor_sync(0xffffffffu, best[s], off);
                int   oc  = __shfl_xor_sync(0xffffffffu, bidx[s], off);
                float ob2 = __shfl_xor_sync(0xffffffffu, bsec[s], off);
                if (ob < best[s] || (ob == best[s] && oc < bidx[s])) {
                    bsec[s] = fminf(best[s], ob2); best[s] = ob; bidx[s] = oc;
                } else {
                    bsec[s] = fminf(bsec[s], ob);
                }
            }
        }
        if (tig == 0) {
            #pragma unroll
            for (int s = 0; s < 4; s++) {
                int mf = s >> 1, rh = s & 1;
                int t = tg * 32 + mf * 16 + rh * 8 + g;
                sRb[t * 2 + cg]  = best[s];
                sRb2[t * 2 + cg] = bsec[s];
                sRi[t * 2 + cg]  = bidx[s];
            }
        }
        __syncthreads();

        // ---- per-token half-result (tid < 128): merge 2 cg, write to global ----
        if (tid < TILTOK) {
            const int t = tid;
            float a1 = sRb[t * 2],     a2 = sRb2[t * 2];     int ai = sRi[t * 2];
            float c1 = sRb[t * 2 + 1], c2 = sRb2[t * 2 + 1]; int ci = sRi[t * 2 + 1];
            float b1, b2; int i1;
            if (c1 < a1) { b1 = c1; i1 = ci; b2 = fminf(a1, c2); }
            else         { b1 = a1; i1 = ai; b2 = fminf(c1, a2); }
            const int gidx = half * NTOK + gtok0 + t;
            g_hb1[gidx] = b1;
            g_hb2[gidx] = b2;
            g_hix[gidx] = i1;
        }
        __syncthreads();
    }
}

// ---------------- k3: merge halves + bound-verified argmin + token outputs ----------------
__global__ void __launch_bounds__(256)
vq_merge(const float* __restrict__ x, float* __restrict__ out) {
    __shared__ float sN[CODES];
    __shared__ float sXn[TILTOK];
    __shared__ int   sIdx[TILTOK];
    const int tid = threadIdx.x;
    const int gtok0 = blockIdx.x * TILTOK;

    sN[tid] = g_norm[tid];
    sN[256 + tid] = g_norm[256 + tid];
    const float maxn2 = __int_as_float(g_maxbits);

    // x into regs (half token per thread) + xnorm
    const int T = tid >> 1, hx = tid & 1;
    float xv[32];
    {
        const float4* xg = (const float4*)(x + (size_t)(gtok0 + T) * DIM + hx * 32);
        float xn = 0.f;
        #pragma unroll
        for (int j = 0; j < 8; j++) {
            float4 v = xg[j];
            xv[4*j] = v.x; xv[4*j+1] = v.y; xv[4*j+2] = v.z; xv[4*j+3] = v.w;
            xn = fmaf(v.x, v.x, xn); xn = fmaf(v.y, v.y, xn);
            xn = fmaf(v.z, v.z, xn); xn = fmaf(v.w, v.w, xn);
        }
        xn += __shfl_xor_sync(0xffffffffu, xn, 1);
        if (hx == 0) sXn[T] = xn;
    }
    __syncthreads();

    if (tid < TILTOK) {
        const int gt = gtok0 + tid;
        float a1 = g_hb1[gt],        a2 = g_hb2[gt];        int ai = g_hix[gt];
        float c1 = g_hb1[NTOK + gt], c2 = g_hb2[NTOK + gt]; int ci = g_hix[NTOK + gt];
        float b1, b2; int i1;
        if (c1 < a1) { b1 = c1; i1 = ci; b2 = fminf(a1, c2); }
        else         { b1 = a1; i1 = ai; b2 = fminf(c1, a2); }   // tie -> half0 (lower codes)

        const float xn = sXn[tid];
        const float B = 3.814697266e-6f * sqrtf(xn * maxn2);   // 2^-18 ||x|| max||e||
        float bd = b1; int bc = i1;
        bool flag = (b2 - b1) < 2.f * B;

        unsigned msk = __ballot_sync(0xffffffffu, flag);
        while (msk) {
            int ld = __ffs(msk) - 1; msk &= msk - 1;
            int rt = (tid & ~31) + ld;
            const float4* xg4 = (const float4*)(x + (size_t)(gtok0 + rt) * DIM);
            float bdw = FLTMAX; int bcw = 0;
            for (int ci2 = 0; ci2 < 16; ci2++) {
                int c = ci2 * 32 + (tid & 31);
                const float4* eg4 = (const float4*)(g_embT + c * DIM);
                float dot = 0.f;
                #pragma unroll
                for (int j = 0; j < 16; j++) {
                    float4 xv4 = xg4[j]; float4 ev4 = eg4[j];
                    dot = fmaf(xv4.x, ev4.x, dot);
                    dot = fmaf(xv4.y, ev4.y, dot);
                    dot = fmaf(xv4.z, ev4.z, dot);
                    dot = fmaf(xv4.w, ev4.w, dot);
                }
                float dd = fmaf(-2.f, dot, sN[c]);
                if (dd < bdw) { bdw = dd; bcw = c; }
            }
            #pragma unroll
            for (int off = 16; off; off >>= 1) {
                float ob = __shfl_xor_sync(0xffffffffu, bdw, off);
                int   oc = __shfl_xor_sync(0xffffffffu, bcw, off);
                if (ob < bdw || (ob == bdw && oc < bcw)) { bdw = ob; bcw = oc; }
            }
            if ((tid & 31) == ld) { bd = bdw; bc = bcw; }
        }

        g_idx[gt] = bc;
        sIdx[tid] = bc;
        out[OFF_IDX + gt] = (float)bc;
        red_f(&g_ni[bc], 1.0f);
        float l = bd + xn;
        #pragma unroll
        for (int o = 16; o; o >>= 1) l += __shfl_xor_sync(0xffffffffu, l, o);
        if ((tid & 31) == 0) red_f(&g_loss, l);
    }
    __syncthreads();

    // eofx from registers
    {
        const int bc = sIdx[T];
        float* gb = g_eofxT + bc * DIM + hx * 32;
        #pragma unroll
        for (int j = 0; j < 16; j++) red_v2(gb + 2 * j, xv[2 * j], xv[2 * j + 1]);
    }
}

// ---------------- k4: post (gather + N + M/emb, block-independent) ----------------
extern __shared__ float sPost[];

__global__ void __launch_bounds__(256)
vq_post(const float* __restrict__ Nin, const float* __restrict__ Min,
        float* __restrict__ out) {
    const int b = blockIdx.x;
    const int tid = threadIdx.x;
    const float DEC = 0.99f, OMD = 1.0f - 0.99f;

    if (b < 256) {
        float* sE = sPost;   // [512][64]
        const float4* src = (const float4*)g_embT;
        float4* dst = (float4*)sE;
        #pragma unroll
        for (int it = 0; it < 32; it++) dst[it * 256 + tid] = src[it * 256 + tid];
        __syncthreads();
        const int warp = tid >> 5, lane = tid & 31;
        const int tbase = b * 1024 + warp * 128;
        int my[4];
        #pragma unroll
        for (int i = 0; i < 4; i++) my[i] = g_idx[tbase + i * 32 + lane];
        #pragma unroll
        for (int i = 0; i < 4; i++) {
            #pragma unroll 8
            for (int s = 0; s < 32; s++) {
                int c = __shfl_sync(0xffffffffu, my[i], s);
                float2 qv = *(const float2*)&sE[c * DIM + lane * 2];
                *(float2*)&out[OFF_Q + (size_t)(tbase + i * 32 + s) * DIM + lane * 2] = qv;
            }
        }
        return;
    }

    float* sNn  = sPost;        // 512
    float* sSum = sPost + 512;  // 256
    #pragma unroll
    for (int h = 0; h < 2; h++) {
        int c = h * 256 + tid;
        sNn[c] = fmaf(Nin[c], DEC, OMD * g_ni[c]);
    }
    __syncthreads();
    sSum[tid] = sNn[tid] + sNn[256 + tid];
    __syncthreads();
    for (int s = 128; s > 0; s >>= 1) {
        if (tid < s) sSum[tid] += sSum[tid + s];
        __syncthreads();
    }
    const float n = sSum[0];

    if (b < 320) {
        #pragma unroll
        for (int h = 0; h < 2; h++) {
            int idx = (b - 256) * 512 + h * 256 + tid;
            int d = idx >> 9, c = idx & (CODES - 1);
            float Ns = (sNn[c] + 1e-5f) / (n + CODES * 1e-5f) * n;
            float Mn = fmaf(Min[idx], DEC, OMD * g_eofxT[c * DIM + d]);
            out[OFF_M + idx] = Mn;
            out[OFF_EMB + idx] = Mn / Ns;
        }
    } else {
        #pragma unroll
        for (int h = 0; h < 2; h++) {
            int c = h * 256 + tid;
            out[OFF_N + c] = sNn[c];
        }
        if (tid == 0) {
            float l = g_loss * (1.0f / 16777216.0f);
            out[OFF_QL] = l;
            out[OFF_CL] = l;
        }
    }
}

extern "C" void kernel_launch(void* const* d_in, const int* in_sizes, int n_in,
                              void* d_out, int out_size) {
    const float* x   = (const float*)d_in[0];
    const float* emb = (const float*)d_in[1];
    const float* N   = (const float*)d_in[2];
    const float* M   = (const float*)d_in[3];
    float* out = (float*)d_out;

    cudaFuncSetAttribute(vq_mma, cudaFuncAttributeMaxDynamicSharedMemorySize, SMEM_BYTES);
    cudaFuncSetAttribute(vq_post, cudaFuncAttributeMaxDynamicSharedMemorySize, 131072);

    vq_split<<<64, 512>>>(emb);
    vq_mma<<<GRID2, TPB, SMEM_BYTES>>>(x);
    vq_merge<<<NTILE, 256>>>(x, out);
    vq_post<<<321, 256, 131072>>>(N, M, out);
}

// round 16
// speedup vs baseline: 1.4861x; 1.4861x over previous
#include <cuda_runtime.h>
#include <cuda_fp16.h>
#include <cstdint>

#define DIM    64
#define CODES  512
#define NTOK   262144
#define TPB    256
#define TILTOK 128
#define NTILE  (NTOK / TILTOK)   // 2048
#define GRID2  152
#define FLTMAX 3.402823466e38f

// Output layout (float32, concatenated tuple)
#define OFF_Q    0L
#define OFF_QL   16777216L
#define OFF_IDX  16777217L
#define OFF_CL   17039361L
#define OFF_EMB  17039362L
#define OFF_N    17072130L
#define OFF_M    17072642L

// vq_mma smem byte offsets
#define SMB_A    0          // A permuted fp16: 32KB
#define SMB_STG  32768      // raw x staging: 32KB
#define SMB_B    65536      // B resident: 128KB
#define SMB_N    196608     // norms: 512 f
#define SMB_XN   198656     // xnorm double buffer: 2 x 128 f
#define SMB_RB   199680     // best: 512 f
#define SMB_RB2  201728     // 2nd best: 512 f
#define SMB_RI   203776     // idx: 512 i
#define SMB_IDX  205824     // final idx: 128 i
#define SMEM_BYTES 206336

__device__ float  g_embT[CODES * DIM];   // [c][d] fp32 (gather + rescan)
__device__ uint4  g_bperm[8192];         // packed fp16-split B fragments (hi,hi,lo,lo)
__device__ float  g_norm[CODES];
__device__ int    g_maxbits;             // max code norm (float bits; positives)
__device__ float  g_ni[CODES];
__device__ float  g_eofxT[CODES * DIM];  // [c][d]
__device__ float  g_loss;
__device__ int    g_idx[NTOK];

// ---------------- helpers ----------------
__device__ __forceinline__ void red_f(float* p, float v) {
    asm volatile("red.global.add.f32 [%0], %1;" :: "l"(p), "f"(v) : "memory");
}
__device__ __forceinline__ void red_v2(float* p, float a, float b) {
    asm volatile("red.global.add.v2.f32 [%0], {%1, %2};" :: "l"(p), "f"(a), "f"(b) : "memory");
}
__device__ __forceinline__ void mma_f16(float* d, const uint4 a, uint32_t b0, uint32_t b1) {
    asm("mma.sync.aligned.m16n8k16.row.col.f32.f16.f16.f32 "
        "{%0,%1,%2,%3}, {%4,%5,%6,%7}, {%8,%9}, {%0,%1,%2,%3};"
        : "+f"(d[0]), "+f"(d[1]), "+f"(d[2]), "+f"(d[3])
        : "r"(a.x), "r"(a.y), "r"(a.z), "r"(a.w), "r"(b0), "r"(b1));
}
__device__ __forceinline__ uint32_t smem_u32(const void* p) {
    uint32_t a;
    asm("{ .reg .u64 t; cvta.to.shared.u64 t, %1; cvt.u32.u64 %0, t; }" : "=r"(a) : "l"(p));
    return a;
}
__device__ __forceinline__ void cp16(uint32_t dst, const void* src) {
    asm volatile("cp.async.cg.shared.global [%0], [%1], 16;" :: "r"(dst), "l"(src) : "memory");
}
#define CP_COMMIT() asm volatile("cp.async.commit_group;" ::: "memory")
#define CP_WAIT0()  asm volatile("cp.async.wait_group 0;" ::: "memory")

__device__ __forceinline__ void split1(float v, __half& h, __half& l) {
    h = __float2half_rn(v);
    l = __float2half_rn(v - __half2float(h));
}

// ---------------- k1: zero + norms + maxnorm + transpose + packed fp16-split B ----------------
__global__ void vq_split(const float* __restrict__ emb) {
    const int idx = blockIdx.x * 512 + threadIdx.x;   // 0..32767

    g_eofxT[idx] = 0.f;
    if (idx < CODES) g_ni[idx] = 0.f;
    if (idx == 0) g_loss = 0.f;

    { int c = idx >> 6, d = idx & 63; g_embT[idx] = emb[d * CODES + c]; }

    if (idx < CODES) {
        float s = 0.f;
        #pragma unroll
        for (int d = 0; d < DIM; d++) {
            float v = emb[d * CODES + idx];
            s = fmaf(v, v, s);
        }
        g_norm[idx] = s;
        atomicMax(&g_maxbits, __float_as_int(s));   // positives: int order == float order
    }

    // B fragment slots: idx = (cfrag*4 + ks)*32 + lane, cfrag = code>>3
    if (idx < 8192) {
        int l  = idx & 31;
        int ks = (idx >> 5) & 3;
        int cf = idx >> 7;
        int n  = cf * 8 + (l >> 2);
        int k0 = ks * 16 + 2 * (l & 3);
        float v00 = emb[k0 * CODES + n];
        float v01 = emb[(k0 + 1) * CODES + n];
        float v10 = emb[(k0 + 8) * CODES + n];
        float v11 = emb[(k0 + 9) * CODES + n];
        __half h00, l00, h01, l01, h10, l10, h11, l11;
        split1(v00, h00, l00); split1(v01, h01, l01);
        split1(v10, h10, l10); split1(v11, h11, l11);
        uint4 o;
        { __half2 t = __halves2half2(h00, h01); o.x = *reinterpret_cast<uint32_t*>(&t); }
        { __half2 t = __halves2half2(h10, h11); o.y = *reinterpret_cast<uint32_t*>(&t); }
        { __half2 t = __halves2half2(l00, l01); o.z = *reinterpret_cast<uint32_t*>(&t); }
        { __half2 t = __halves2half2(l10, l11); o.w = *reinterpret_cast<uint32_t*>(&t); }
        g_bperm[idx] = o;
    }
}

// ---------------- k2: persistent pipelined fp16 3-term MMA + verified argmin ----------------
extern __shared__ char sm[];

// stage raw x tile (128 tokens x 64 f32 = 32KB) via cp.async
__device__ __forceinline__ void stage_x(const float* x, int tile, uint32_t smbase, int tid) {
    const char* src = (const char*)(x + (size_t)tile * TILTOK * DIM);
    #pragma unroll
    for (int i = 0; i < 8; i++) {
        int off = (i * 256 + tid) * 16;
        cp16(smbase + SMB_STG + off, src + off);
    }
    CP_COMMIT();
}

// permute staged x -> A (fp16 hi/lo, mma fragment layout) + per-token xnorm
__device__ __forceinline__ void permute_tile(float* sXn, int tid) {
    const char* stg = sm + SMB_STG;
    #pragma unroll
    for (int j = 0; j < 8; j++) {
        int idx = j * 256 + tid;
        float4 v = *(const float4*)(stg + idx * 16);
        int tt = j * 16 + (tid >> 4);
        int q  = tid & 15;
        float qn = fmaf(v.x, v.x, fmaf(v.y, v.y, fmaf(v.z, v.z, v.w * v.w)));
        qn += __shfl_xor_sync(0xffffffffu, qn, 1);
        qn += __shfl_xor_sync(0xffffffffu, qn, 2);
        qn += __shfl_xor_sync(0xffffffffu, qn, 4);
        qn += __shfl_xor_sync(0xffffffffu, qn, 8);
        if (q == 0) sXn[tt] = qn;
        #pragma unroll
        for (int pp = 0; pp < 2; pp++) {
            float a = pp ? v.z : v.x;
            float b = pp ? v.w : v.y;
            int k = 4 * q + 2 * pp;
            int ks = k >> 4, kk = k & 15;
            int sel8 = kk >> 3, ktig = (kk & 7) >> 1;
            int areg = sel8 * 2 + ((tt >> 3) & 1);
            int slot = ((tt >> 4) * 4 + ks) * 2;
            uint32_t byte = (uint32_t)slot * 512 + (uint32_t)(tt & 7) * 64
                          + (uint32_t)ktig * 16 + (uint32_t)areg * 4;
            __half2 hh = __floats2half2_rn(a, b);
            float2 wf = __half22float2(hh);
            __half2 ll = __floats2half2_rn(a - wf.x, b - wf.y);
            *(uint32_t*)(sm + SMB_A + byte)       = *reinterpret_cast<uint32_t*>(&hh);
            *(uint32_t*)(sm + SMB_A + byte + 512) = *reinterpret_cast<uint32_t*>(&ll);
        }
    }
}

__global__ void __launch_bounds__(TPB, 1)
vq_mma(const float* __restrict__ x, float* __restrict__ out) {
    const int tid  = threadIdx.x;
    const int lane = tid & 31, wid = tid >> 5;
    const int tg = wid & 1;          // token group (64 tokens)
    const int cg = wid >> 1;         // code group (128 codes)
    const int g  = lane >> 2;
    const int tig = lane & 3;

    float* sN   = (float*)(sm + SMB_N);
    float* sXn  = (float*)(sm + SMB_XN);
    float* sRb  = (float*)(sm + SMB_RB);
    float* sRb2 = (float*)(sm + SMB_RB2);
    int*   sRi  = (int*)(sm + SMB_RI);
    int*   sIdx = (int*)(sm + SMB_IDX);
    const uint32_t smbase = smem_u32(sm);
    const float maxn2 = __int_as_float(g_maxbits);

    sN[tid] = g_norm[tid];
    sN[256 + tid] = g_norm[256 + tid];

    // one-time: B resident (128KB) + first x tile staged, one cp.async group
    {
        const char* src = (const char*)g_bperm;
        #pragma unroll
        for (int i = 0; i < 32; i++) {
            int off = (i * 256 + tid) * 16;
            cp16(smbase + SMB_B + off, src + off);
        }
    }
    int tile = blockIdx.x;
    stage_x(x, tile, smbase, tid);
    CP_WAIT0();
    __syncthreads();
    permute_tile(sXn, tid);          // phase 0
    __syncthreads();
    if (tile + GRID2 < NTILE) stage_x(x, tile + GRID2, smbase, tid);
    int p = 0;

    for (; tile < NTILE; tile += GRID2) {
        const int gtok0 = tile * TILTOK;

        // ---- mainloop: warp covers 64 tokens x 128 codes; 3 split terms ----
        float best[8], bsec[8]; int bidx[8];
        #pragma unroll
        for (int s = 0; s < 8; s++) { best[s] = FLTMAX; bsec[s] = FLTMAX; bidx[s] = 0; }

        #pragma unroll
        for (int ch = 0; ch < 4; ch++) {
            float acc[4][4][4];
            #pragma unroll
            for (int mf = 0; mf < 4; mf++)
                #pragma unroll
                for (int j = 0; j < 4; j++)
                    #pragma unroll
                    for (int q = 0; q < 4; q++) acc[mf][j][q] = 0.f;

            #pragma unroll
            for (int ks = 0; ks < 4; ks++) {
                uint4 af[4][2];
                #pragma unroll
                for (int mf = 0; mf < 4; mf++)
                    #pragma unroll
                    for (int hl = 0; hl < 2; hl++)
                        af[mf][hl] = *(const uint4*)(sm + SMB_A +
                            (((tg * 4 + mf) * 4 + ks) * 2 + hl) * 512 + lane * 16);
                uint4 bf[4];
                #pragma unroll
                for (int j = 0; j < 4; j++)
                    bf[j] = *(const uint4*)(sm + SMB_B +
                        ((cg * 16 + ch * 4 + j) * 4 + ks) * 512 + lane * 16);
                #pragma unroll
                for (int mf = 0; mf < 4; mf++) {
                    #pragma unroll
                    for (int j = 0; j < 4; j++) {
                        mma_f16(acc[mf][j], af[mf][0], bf[j].x, bf[j].y);  // xh·eh
                        mma_f16(acc[mf][j], af[mf][0], bf[j].z, bf[j].w);  // xh·el
                        mma_f16(acc[mf][j], af[mf][1], bf[j].x, bf[j].y);  // xl·eh
                    }
                }
            }
            // epilogue chunk: dist + top-2 (codes ascending)
            #pragma unroll
            for (int j = 0; j < 4; j++) {
                int c0 = cg * 128 + (ch * 4 + j) * 8 + 2 * tig;
                float n0 = sN[c0], n1 = sN[c0 + 1];
                #pragma unroll
                for (int mf = 0; mf < 4; mf++) {
                    float dv[4];
                    dv[0] = fmaf(-2.f, acc[mf][j][0], n0);
                    dv[1] = fmaf(-2.f, acc[mf][j][1], n1);
                    dv[2] = fmaf(-2.f, acc[mf][j][2], n0);
                    dv[3] = fmaf(-2.f, acc[mf][j][3], n1);
                    #pragma unroll
                    for (int q = 0; q < 4; q++) {
                        int s = mf * 2 + (q >> 1);
                        int c = c0 + (q & 1);
                        if (dv[q] < best[s]) { bsec[s] = best[s]; best[s] = dv[q]; bidx[s] = c; }
                        else if (dv[q] < bsec[s]) bsec[s] = dv[q];
                    }
                }
            }
        }

        // merge across tig lanes (same tokens)
        #pragma unroll
        for (int off = 1; off <= 2; off <<= 1) {
            #pragma unroll
            for (int s = 0; s < 8; s++) {
                float ob  = __shfl_xor_sync(0xffffffffu, best[s], off);
                int   oc  = __shfl_xor_sync(0xffffffffu, bidx[s], off);
                float ob2 = __shfl_xor_sync(0xffffffffu, bsec[s], off);
                if (ob < best[s] || (ob == best[s] && oc < bidx[s])) {
                    bsec[s] = fminf(best[s], ob2); best[s] = ob; bidx[s] = oc;
                } else {
                    bsec[s] = fminf(bsec[s], ob);
                }
            }
        }
        if (tig == 0) {
            #pragma unroll
            for (int s = 0; s < 8; s++) {
                int mf = s >> 1, rh = s & 1;
                int t = tg * 64 + mf * 16 + rh * 8 + g;
                sRb[t * 4 + cg]  = best[s];
                sRb2[t * 4 + cg] = bsec[s];
                sRi[t * 4 + cg]  = bidx[s];
            }
        }
        __syncthreads();   // bar1

        // ---- per-token finalize + verify (tid < 128) ----
        if (tid < TILTOK) {
            const int t = tid;
            float b1 = sRb[t * 4]; int i1 = sRi[t * 4]; float b2 = sRb2[t * 4];
            #pragma unroll
            for (int s = 1; s < 4; s++) {
                float ob = sRb[t * 4 + s]; int oc = sRi[t * 4 + s]; float ob2 = sRb2[t * 4 + s];
                if (ob < b1 || (ob == b1 && oc < i1)) { b2 = fminf(b1, ob2); b1 = ob; i1 = oc; }
                else b2 = fminf(b2, ob);
            }
            const float xn = sXn[(p << 7) + t];
            const float B = 3.814697266e-6f * sqrtf(xn * maxn2);   // 2^-18 ||x|| max||e||
            float bd = b1; int bc = i1;
            bool flag = (b2 - b1) < 2.f * B;

            unsigned msk = __ballot_sync(0xffffffffu, flag);
            while (msk) {
                int ld = __ffs(msk) - 1; msk &= msk - 1;
                int rt = (tid & ~31) + ld;
                const float4* xg4 = (const float4*)(x + (size_t)(gtok0 + rt) * DIM);
                float bdw = FLTMAX; int bcw = 0;
                for (int ci = 0; ci < 16; ci++) {
                    int c = ci * 32 + (tid & 31);
                    const float4* eg4 = (const float4*)(g_embT + c * DIM);
                    float dot = 0.f;
                    #pragma unroll
                    for (int j = 0; j < 16; j++) {
                        float4 xv4 = xg4[j]; float4 ev4 = eg4[j];
                        dot = fmaf(xv4.x, ev4.x, dot);
                        dot = fmaf(xv4.y, ev4.y, dot);
                        dot = fmaf(xv4.z, ev4.z, dot);
                        dot = fmaf(xv4.w, ev4.w, dot);
                    }
                    float dd = fmaf(-2.f, dot, sN[c]);
                    if (dd < bdw) { bdw = dd; bcw = c; }
                }
                #pragma unroll
                for (int off = 16; off; off >>= 1) {
                    float ob = __shfl_xor_sync(0xffffffffu, bdw, off);
                    int   oc = __shfl_xor_sync(0xffffffffu, bcw, off);
                    if (ob < bdw || (ob == bdw && oc < bcw)) { bdw = ob; bcw = oc; }
                }
                if ((tid & 31) == ld) { bd = bdw; bc = bcw; }
            }

            const int gt = gtok0 + t;
            g_idx[gt] = bc;
            sIdx[t] = bc;
            out[OFF_IDX + gt] = (float)bc;
            red_f(&g_ni[bc], 1.0f);
            float l = bd + xn;
            #pragma unroll
            for (int o = 16; o; o >>= 1) l += __shfl_xor_sync(0xffffffffu, l, o);
            if ((tid & 31) == 0) red_f(&g_loss, l);
        }
        __syncthreads();   // bar2

        // ---- eofx scatter: all 256 threads, half token each (x from L2) ----
        {
            const int T = tid >> 1, hx = tid & 1;
            const int bc = sIdx[T];
            float* gb = g_eofxT + bc * DIM + hx * 32;
            const float4* xg = (const float4*)(x + (size_t)(gtok0 + T) * DIM + hx * 32);
            #pragma unroll
            for (int j = 0; j < 8; j++) {
                float4 v = xg[j];
                red_v2(gb + 4 * j, v.x, v.y);
                red_v2(gb + 4 * j + 2, v.z, v.w);
            }
        }

        // ---- pipeline: permute next tile from staging ----
        const int nxt = tile + GRID2;
        if (nxt < NTILE) {
            CP_WAIT0();
            permute_tile(sXn + ((p ^ 1) << 7), tid);
        }
        __syncthreads();   // bar3
        if (nxt + GRID2 < NTILE) stage_x(x, nxt + GRID2, smbase, tid);
        p ^= 1;
    }
}

// ---------------- k3: post (gather + N + M/emb, block-independent) ----------------
extern __shared__ float sPost[];

__global__ void __launch_bounds__(256)
vq_post(const float* __restrict__ Nin, const float* __restrict__ Min,
        float* __restrict__ out) {
    const int b = blockIdx.x;
    const int tid = threadIdx.x;
    const float DEC = 0.99f, OMD = 1.0f - 0.99f;

    if (b < 256) {
        float* sE = sPost;   // [512][64]
        const float4* src = (const float4*)g_embT;
        float4* dst = (float4*)sE;
        #pragma unroll
        for (int it = 0; it < 32; it++) dst[it * 256 + tid] = src[it * 256 + tid];
        __syncthreads();
        const int warp = tid >> 5, lane = tid & 31;
        const int tbase = b * 1024 + warp * 128;
        int my[4];
        #pragma unroll
        for (int i = 0; i < 4; i++) my[i] = g_idx[tbase + i * 32 + lane];
        #pragma unroll
        for (int i = 0; i < 4; i++) {
            #pragma unroll 8
            for (int s = 0; s < 32; s++) {
                int c = __shfl_sync(0xffffffffu, my[i], s);
                float2 qv = *(const float2*)&sE[c * DIM + lane * 2];
                *(float2*)&out[OFF_Q + (size_t)(tbase + i * 32 + s) * DIM + lane * 2] = qv;
            }
        }
        return;
    }

    float* sNn  = sPost;        // 512
    float* sSum = sPost + 512;  // 256
    #pragma unroll
    for (int h = 0; h < 2; h++) {
        int c = h * 256 + tid;
        sNn[c] = fmaf(Nin[c], DEC, OMD * g_ni[c]);
    }
    __syncthreads();
    sSum[tid] = sNn[tid] + sNn[256 + tid];
    __syncthreads();
    for (int s = 128; s > 0; s >>= 1) {
        if (tid < s) sSum[tid] += sSum[tid + s];
        __syncthreads();
    }
    const float n = sSum[0];

    if (b < 320) {
        #pragma unroll
        for (int h = 0; h < 2; h++) {
            int idx = (b - 256) * 512 + h * 256 + tid;
            int d = idx >> 9, c = idx & (CODES - 1);
            float Ns = (sNn[c] + 1e-5f) / (n + CODES * 1e-5f) * n;
            float Mn = fmaf(Min[idx], DEC, OMD * g_eofxT[c * DIM + d]);
            out[OFF_M + idx] = Mn;
            out[OFF_EMB + idx] = Mn / Ns;
        }
    } else {
        #pragma unroll
        for (int h = 0; h < 2; h++) {
            int c = h * 256 + tid;
            out[OFF_N + c] = sNn[c];
        }
        if (tid == 0) {
            float l = g_loss * (1.0f / 16777216.0f);
            out[OFF_QL] = l;
            out[OFF_CL] = l;
        }
    }
}

extern "C" void kernel_launch(void* const* d_in, const int* in_sizes, int n_in,
                              void* d_out, int out_size) {
    const float* x   = (const float*)d_in[0];
    const float* emb = (const float*)d_in[1];
    const float* N   = (const float*)d_in[2];
    const float* M   = (const float*)d_in[3];
    float* out = (float*)d_out;

    cudaFuncSetAttribute(vq_mma, cudaFuncAttributeMaxDynamicSharedMemorySize, SMEM_BYTES);
    cudaFuncSetAttribute(vq_post, cudaFuncAttributeMaxDynamicSharedMemorySize, 131072);

    vq_split<<<64, 512>>>(emb);
    vq_mma<<<GRID2, TPB, SMEM_BYTES>>>(x, out);
    vq_post<<<321, 256, 131072>>>(N, M, out);
}

// round 17
// speedup vs baseline: 1.5934x; 1.0722x over previous
#include <cuda_runtime.h>
#include <cuda_fp16.h>
#include <cstdint>

#define DIM    64
#define CODES  512
#define NTOK   262144
#define TPB    512
#define TILTOK 128
#define NTILE  (NTOK / TILTOK)   // 2048
#define GRID2  152
#define FLTMAX 3.402823466e38f

// Output layout (float32, concatenated tuple)
#define OFF_Q    0L
#define OFF_QL   16777216L
#define OFF_IDX  16777217L
#define OFF_CL   17039361L
#define OFF_EMB  17039362L
#define OFF_N    17072130L
#define OFF_M    17072642L

// vq_mma smem byte offsets
#define SMB_A    0          // A permuted fp16: 32KB
#define SMB_STG  32768      // raw x staging: 32KB
#define SMB_B    65536      // B resident: 128KB
#define SMB_N    196608     // norms: 512 f
#define SMB_XN   198656     // xnorm double buffer: 2 x 128 f
#define SMB_RB   199680     // best: 512 f
#define SMB_RB2  201728     // 2nd best: 512 f
#define SMB_RI   203776     // idx: 512 i
#define SMB_IDX  205824     // final idx: 128 i
#define SMEM_BYTES 206336

__device__ float  g_embT[CODES * DIM];   // [c][d] fp32 (gather + rescan)
__device__ uint4  g_bperm[8192];         // packed fp16-split B fragments (hi,hi,lo,lo)
__device__ float  g_norm[CODES];
__device__ int    g_maxbits;             // max code norm (float bits; positives)
__device__ float  g_ni[CODES];
__device__ float  g_eofxT[CODES * DIM];  // [c][d]
__device__ float  g_loss;
__device__ int    g_idx[NTOK];

// ---------------- helpers ----------------
__device__ __forceinline__ void red_f(float* p, float v) {
    asm volatile("red.global.add.f32 [%0], %1;" :: "l"(p), "f"(v) : "memory");
}
__device__ __forceinline__ void red_v2(float* p, float a, float b) {
    asm volatile("red.global.add.v2.f32 [%0], {%1, %2};" :: "l"(p), "f"(a), "f"(b) : "memory");
}
__device__ __forceinline__ void mma_f16(float* d, const uint4 a, uint32_t b0, uint32_t b1) {
    asm("mma.sync.aligned.m16n8k16.row.col.f32.f16.f16.f32 "
        "{%0,%1,%2,%3}, {%4,%5,%6,%7}, {%8,%9}, {%0,%1,%2,%3};"
        : "+f"(d[0]), "+f"(d[1]), "+f"(d[2]), "+f"(d[3])
        : "r"(a.x), "r"(a.y), "r"(a.z), "r"(a.w), "r"(b0), "r"(b1));
}
__device__ __forceinline__ uint32_t smem_u32(const void* p) {
    uint32_t a;
    asm("{ .reg .u64 t; cvta.to.shared.u64 t, %1; cvt.u32.u64 %0, t; }" : "=r"(a) : "l"(p));
    return a;
}
__device__ __forceinline__ void cp16(uint32_t dst, const void* src) {
    asm volatile("cp.async.cg.shared.global [%0], [%1], 16;" :: "r"(dst), "l"(src) : "memory");
}
#define CP_COMMIT() asm volatile("cp.async.commit_group;" ::: "memory")
#define CP_WAIT0()  asm volatile("cp.async.wait_group 0;" ::: "memory")

__device__ __forceinline__ void split1(float v, __half& h, __half& l) {
    h = __float2half_rn(v);
    l = __float2half_rn(v - __half2float(h));
}

// ---------------- k1: zero + norms + maxnorm + transpose + packed fp16-split B ----------------
__global__ void vq_split(const float* __restrict__ emb) {
    const int idx = blockIdx.x * 512 + threadIdx.x;   // 0..32767

    g_eofxT[idx] = 0.f;
    if (idx < CODES) g_ni[idx] = 0.f;
    if (idx == 0) g_loss = 0.f;

    { int c = idx >> 6, d = idx & 63; g_embT[idx] = emb[d * CODES + c]; }

    if (idx < CODES) {
        float s = 0.f;
        #pragma unroll
        for (int d = 0; d < DIM; d++) {
            float v = emb[d * CODES + idx];
            s = fmaf(v, v, s);
        }
        g_norm[idx] = s;
        atomicMax(&g_maxbits, __float_as_int(s));   // positives: int order == float order
    }

    // B fragment slots: idx = (cfrag*4 + ks)*32 + lane, cfrag = code>>3
    if (idx < 8192) {
        int l  = idx & 31;
        int ks = (idx >> 5) & 3;
        int cf = idx >> 7;
        int n  = cf * 8 + (l >> 2);
        int k0 = ks * 16 + 2 * (l & 3);
        float v00 = emb[k0 * CODES + n];
        float v01 = emb[(k0 + 1) * CODES + n];
        float v10 = emb[(k0 + 8) * CODES + n];
        float v11 = emb[(k0 + 9) * CODES + n];
        __half h00, l00, h01, l01, h10, l10, h11, l11;
        split1(v00, h00, l00); split1(v01, h01, l01);
        split1(v10, h10, l10); split1(v11, h11, l11);
        uint4 o;
        { __half2 t = __halves2half2(h00, h01); o.x = *reinterpret_cast<uint32_t*>(&t); }
        { __half2 t = __halves2half2(h10, h11); o.y = *reinterpret_cast<uint32_t*>(&t); }
        { __half2 t = __halves2half2(l00, l01); o.z = *reinterpret_cast<uint32_t*>(&t); }
        { __half2 t = __halves2half2(l10, l11); o.w = *reinterpret_cast<uint32_t*>(&t); }
        g_bperm[idx] = o;
    }
}

// ---------------- k2: persistent pipelined fp16 3-term MMA + verified argmin ----------------
extern __shared__ char sm[];

// stage raw x tile (128 tokens x 64 f32 = 32KB) via cp.async
__device__ __forceinline__ void stage_x(const float* x, int tile, uint32_t smbase, int tid) {
    const char* src = (const char*)(x + (size_t)tile * TILTOK * DIM);
    #pragma unroll
    for (int i = 0; i < 4; i++) {
        int off = (i * TPB + tid) * 16;
        cp16(smbase + SMB_STG + off, src + off);
    }
    CP_COMMIT();
}

// permute staged x -> A (fp16 hi/lo, mma fragment layout) + per-token xnorm
__device__ __forceinline__ void permute_tile(float* sXn, int tid) {
    const char* stg = sm + SMB_STG;
    #pragma unroll
    for (int j = 0; j < 4; j++) {
        int idx = j * TPB + tid;
        float4 v = *(const float4*)(stg + idx * 16);
        int tt = idx >> 4;
        int q  = tid & 15;
        float qn = fmaf(v.x, v.x, fmaf(v.y, v.y, fmaf(v.z, v.z, v.w * v.w)));
        qn += __shfl_xor_sync(0xffffffffu, qn, 1);
        qn += __shfl_xor_sync(0xffffffffu, qn, 2);
        qn += __shfl_xor_sync(0xffffffffu, qn, 4);
        qn += __shfl_xor_sync(0xffffffffu, qn, 8);
        if (q == 0) sXn[tt] = qn;
        #pragma unroll
        for (int pp = 0; pp < 2; pp++) {
            float a = pp ? v.z : v.x;
            float b = pp ? v.w : v.y;
            int k = 4 * q + 2 * pp;
            int ks = k >> 4, kk = k & 15;
            int sel8 = kk >> 3, ktig = (kk & 7) >> 1;
            int areg = sel8 * 2 + ((tt >> 3) & 1);
            int slot = ((tt >> 4) * 4 + ks) * 2;
            uint32_t byte = (uint32_t)slot * 512 + (uint32_t)(tt & 7) * 64
                          + (uint32_t)ktig * 16 + (uint32_t)areg * 4;
            __half2 hh = __floats2half2_rn(a, b);
            float2 wf = __half22float2(hh);
            __half2 ll = __floats2half2_rn(a - wf.x, b - wf.y);
            *(uint32_t*)(sm + SMB_A + byte)       = *reinterpret_cast<uint32_t*>(&hh);
            *(uint32_t*)(sm + SMB_A + byte + 512) = *reinterpret_cast<uint32_t*>(&ll);
        }
    }
}

__global__ void __launch_bounds__(TPB, 1)
vq_mma(const float* __restrict__ x, float* __restrict__ out) {
    const int tid  = threadIdx.x;
    const int lane = tid & 31, wid = tid >> 5;
    const int tg = wid & 3;          // token group (32 tokens)
    const int cg = wid >> 2;         // code group (128 codes)
    const int g  = lane >> 2;
    const int tig = lane & 3;

    float* sN   = (float*)(sm + SMB_N);
    float* sXn  = (float*)(sm + SMB_XN);
    float* sRb  = (float*)(sm + SMB_RB);
    float* sRb2 = (float*)(sm + SMB_RB2);
    int*   sRi  = (int*)(sm + SMB_RI);
    int*   sIdx = (int*)(sm + SMB_IDX);
    const uint32_t smbase = smem_u32(sm);
    const float maxn2 = __int_as_float(g_maxbits);

    sN[tid] = g_norm[tid];

    // one-time: B resident (128KB) + first x tile staged, one cp.async group
    {
        const char* src = (const char*)g_bperm;
        #pragma unroll
        for (int i = 0; i < 16; i++) {
            int off = (i * TPB + tid) * 16;
            cp16(smbase + SMB_B + off, src + off);
        }
    }
    int tile = blockIdx.x;
    stage_x(x, tile, smbase, tid);
    CP_WAIT0();
    __syncthreads();
    permute_tile(sXn, tid);          // phase 0
    __syncthreads();
    if (tile + GRID2 < NTILE) stage_x(x, tile + GRID2, smbase, tid);
    int p = 0;

    for (; tile < NTILE; tile += GRID2) {
        const int gtok0 = tile * TILTOK;

        // ---- mainloop: warp covers 32 tokens x 128 codes; 3 split terms ----
        float best[4], bsec[4]; int bidx[4];
        #pragma unroll
        for (int s = 0; s < 4; s++) { best[s] = FLTMAX; bsec[s] = FLTMAX; bidx[s] = 0; }

        #pragma unroll
        for (int ch = 0; ch < 4; ch++) {
            float acc[2][4][4];
            #pragma unroll
            for (int mf = 0; mf < 2; mf++)
                #pragma unroll
                for (int j = 0; j < 4; j++)
                    #pragma unroll
                    for (int q = 0; q < 4; q++) acc[mf][j][q] = 0.f;

            #pragma unroll
            for (int ks = 0; ks < 4; ks++) {
                uint4 af[2][2];
                #pragma unroll
                for (int mf = 0; mf < 2; mf++)
                    #pragma unroll
                    for (int hl = 0; hl < 2; hl++)
                        af[mf][hl] = *(const uint4*)(sm + SMB_A +
                            (((tg * 2 + mf) * 4 + ks) * 2 + hl) * 512 + lane * 16);
                uint4 bf[4];
                #pragma unroll
                for (int j = 0; j < 4; j++)
                    bf[j] = *(const uint4*)(sm + SMB_B +
                        ((cg * 16 + ch * 4 + j) * 4 + ks) * 512 + lane * 16);
                #pragma unroll
                for (int mf = 0; mf < 2; mf++) {
                    #pragma unroll
                    for (int j = 0; j < 4; j++) {
                        mma_f16(acc[mf][j], af[mf][0], bf[j].x, bf[j].y);  // xh·eh
                        mma_f16(acc[mf][j], af[mf][0], bf[j].z, bf[j].w);  // xh·el
                        mma_f16(acc[mf][j], af[mf][1], bf[j].x, bf[j].y);  // xl·eh
                    }
                }
            }
            // epilogue chunk: dist + top-2 (codes ascending)
            #pragma unroll
            for (int j = 0; j < 4; j++) {
                int c0 = cg * 128 + (ch * 4 + j) * 8 + 2 * tig;
                float n0 = sN[c0], n1 = sN[c0 + 1];
                #pragma unroll
                for (int mf = 0; mf < 2; mf++) {
                    float dv[4];
                    dv[0] = fmaf(-2.f, acc[mf][j][0], n0);
                    dv[1] = fmaf(-2.f, acc[mf][j][1], n1);
                    dv[2] = fmaf(-2.f, acc[mf][j][2], n0);
                    dv[3] = fmaf(-2.f, acc[mf][j][3], n1);
                    #pragma unroll
                    for (int q = 0; q < 4; q++) {
                        int s = mf * 2 + (q >> 1);
                        int c = c0 + (q & 1);
                        if (dv[q] < best[s]) { bsec[s] = best[s]; best[s] = dv[q]; bidx[s] = c; }
                        else if (dv[q] < bsec[s]) bsec[s] = dv[q];
                    }
                }
            }
        }

        // merge across tig lanes (same tokens)
        #pragma unroll
        for (int off = 1; off <= 2; off <<= 1) {
            #pragma unroll
            for (int s = 0; s < 4; s++) {
                float ob  = __shfl_xor_sync(0xffffffffu, best[s], off);
                int   oc  = __shfl_xor_sync(0xffffffffu, bidx[s], off);
                float ob2 = __shfl_xor_sync(0xffffffffu, bsec[s], off);
                if (ob < best[s] || (ob == best[s] && oc < bidx[s])) {
                    bsec[s] = fminf(best[s], ob2); best[s] = ob; bidx[s] = oc;
                } else {
                    bsec[s] = fminf(bsec[s], ob);
                }
            }
        }
        if (tig == 0) {
            #pragma unroll
            for (int s = 0; s < 4; s++) {
                int mf = s >> 1, rh = s & 1;
                int t = tg * 32 + mf * 16 + rh * 8 + g;
                sRb[t * 4 + cg]  = best[s];
                sRb2[t * 4 + cg] = bsec[s];
                sRi[t * 4 + cg]  = bidx[s];
            }
        }
        __syncthreads();   // bar1

        // ---- per-token finalize + verify (tid < 128) ----
        if (tid < TILTOK) {
            const int t = tid;
            float b1 = sRb[t * 4]; int i1 = sRi[t * 4]; float b2 = sRb2[t * 4];
            #pragma unroll
            for (int s = 1; s < 4; s++) {
                float ob = sRb[t * 4 + s]; int oc = sRi[t * 4 + s]; float ob2 = sRb2[t * 4 + s];
                if (ob < b1 || (ob == b1 && oc < i1)) { b2 = fminf(b1, ob2); b1 = ob; i1 = oc; }
                else b2 = fminf(b2, ob);
            }
            const float xn = sXn[(p << 7) + t];
            const float B = 3.814697266e-6f * sqrtf(xn * maxn2);   // 2^-18 ||x|| max||e||
            float bd = b1; int bc = i1;
            bool flag = (b2 - b1) < 2.f * B;

            unsigned msk = __ballot_sync(0xffffffffu, flag);
            while (msk) {
                int ld = __ffs(msk) - 1; msk &= msk - 1;
                int rt = (tid & ~31) + ld;
                const float4* xg4 = (const float4*)(x + (size_t)(gtok0 + rt) * DIM);
                float bdw = FLTMAX; int bcw = 0;
                for (int ci = 0; ci < 16; ci++) {
                    int c = ci * 32 + (tid & 31);
                    const float4* eg4 = (const float4*)(g_embT + c * DIM);
                    float dot = 0.f;
                    #pragma unroll
                    for (int j = 0; j < 16; j++) {
                        float4 xv4 = xg4[j]; float4 ev4 = eg4[j];
                        dot = fmaf(xv4.x, ev4.x, dot);
                        dot = fmaf(xv4.y, ev4.y, dot);
                        dot = fmaf(xv4.z, ev4.z, dot);
                        dot = fmaf(xv4.w, ev4.w, dot);
                    }
                    float dd = fmaf(-2.f, dot, sN[c]);
                    if (dd < bdw) { bdw = dd; bcw = c; }
                }
                #pragma unroll
                for (int off = 16; off; off >>= 1) {
                    float ob = __shfl_xor_sync(0xffffffffu, bdw, off);
                    int   oc = __shfl_xor_sync(0xffffffffu, bcw, off);
                    if (ob < bdw || (ob == bdw && oc < bcw)) { bdw = ob; bcw = oc; }
                }
                if ((tid & 31) == ld) { bd = bdw; bc = bcw; }
            }

            const int gt = gtok0 + t;
            g_idx[gt] = bc;
            sIdx[t] = bc;
            out[OFF_IDX + gt] = (float)bc;
            red_f(&g_ni[bc], 1.0f);
            float l = bd + xn;
            #pragma unroll
            for (int o = 16; o; o >>= 1) l += __shfl_xor_sync(0xffffffffu, l, o);
            if ((tid & 31) == 0) red_f(&g_loss, l);
        }
        __syncthreads();   // bar2

        // ---- eofx scatter: all 512 threads, quarter token each (x from L2) ----
        {
            const int T = tid >> 2, qx = tid & 3;
            const int bc = sIdx[T];
            float* gb = g_eofxT + bc * DIM + qx * 16;
            const float4* xg = (const float4*)(x + (size_t)(gtok0 + T) * DIM + qx * 16);
            #pragma unroll
            for (int j = 0; j < 4; j++) {
                float4 v = xg[j];
                red_v2(gb + 4 * j, v.x, v.y);
                red_v2(gb + 4 * j + 2, v.z, v.w);
            }
        }

        // ---- pipeline: permute next tile from staging ----
        const int nxt = tile + GRID2;
        if (nxt < NTILE) {
            CP_WAIT0();
            permute_tile(sXn + ((p ^ 1) << 7), tid);
        }
        __syncthreads();   // bar3
        if (nxt + GRID2 < NTILE) stage_x(x, nxt + GRID2, smbase, tid);
        p ^= 1;
    }
}

// ---------------- k3: post (gather + N + M/emb, block-independent) ----------------
extern __shared__ float sPost[];

__global__ void __launch_bounds__(256)
vq_post(const float* __restrict__ Nin, const float* __restrict__ Min,
        float* __restrict__ out) {
    const int b = blockIdx.x;
    const int tid = threadIdx.x;
    const float DEC = 0.99f, OMD = 1.0f - 0.99f;

    if (b < 256) {
        float* sE = sPost;   // [512][64]
        const float4* src = (const float4*)g_embT;
        float4* dst = (float4*)sE;
        #pragma unroll
        for (int it = 0; it < 32; it++) dst[it * 256 + tid] = src[it * 256 + tid];
        __syncthreads();
        const int warp = tid >> 5, lane = tid & 31;
        const int tbase = b * 1024 + warp * 128;
        int my[4];
        #pragma unroll
        for (int i = 0; i < 4; i++) my[i] = g_idx[tbase + i * 32 + lane];
        #pragma unroll
        for (int i = 0; i < 4; i++) {
            #pragma unroll 8
            for (int s = 0; s < 32; s++) {
                int c = __shfl_sync(0xffffffffu, my[i], s);
                float2 qv = *(const float2*)&sE[c * DIM + lane * 2];
                *(float2*)&out[OFF_Q + (size_t)(tbase + i * 32 + s) * DIM + lane * 2] = qv;
            }
        }
        return;
    }

    float* sNn  = sPost;        // 512
    float* sSum = sPost + 512;  // 256
    #pragma unroll
    for (int h = 0; h < 2; h++) {
        int c = h * 256 + tid;
        sNn[c] = fmaf(Nin[c], DEC, OMD * g_ni[c]);
    }
    __syncthreads();
    sSum[tid] = sNn[tid] + sNn[256 + tid];
    __syncthreads();
    for (int s = 128; s > 0; s >>= 1) {
        if (tid < s) sSum[tid] += sSum[tid + s];
        __syncthreads();
    }
    const float n = sSum[0];

    if (b < 320) {
        #pragma unroll
        for (int h = 0; h < 2; h++) {
            int idx = (b - 256) * 512 + h * 256 + tid;
            int d = idx >> 9, c = idx & (CODES - 1);
            float Ns = (sNn[c] + 1e-5f) / (n + CODES * 1e-5f) * n;
            float Mn = fmaf(Min[idx], DEC, OMD * g_eofxT[c * DIM + d]);
            out[OFF_M + idx] = Mn;
            out[OFF_EMB + idx] = Mn / Ns;
        }
    } else {
        #pragma unroll
        for (int h = 0; h < 2; h++) {
            int c = h * 256 + tid;
            out[OFF_N + c] = sNn[c];
        }
        if (tid == 0) {
            float l = g_loss * (1.0f / 16777216.0f);
            out[OFF_QL] = l;
            out[OFF_CL] = l;
        }
    }
}

extern "C" void kernel_launch(void* const* d_in, const int* in_sizes, int n_in,
                              void* d_out, int out_size) {
    const float* x   = (const float*)d_in[0];
    const float* emb = (const float*)d_in[1];
    const float* N   = (const float*)d_in[2];
    const float* M   = (const float*)d_in[3];
    float* out = (float*)d_out;

    cudaFuncSetAttribute(vq_mma, cudaFuncAttributeMaxDynamicSharedMemorySize, SMEM_BYTES);
    cudaFuncSetAttribute(vq_post, cudaFuncAttributeMaxDynamicSharedMemorySize, 131072);

    vq_split<<<64, 512>>>(emb);
    vq_mma<<<GRID2, TPB, SMEM_BYTES>>>(x, out);
    vq_post<<<321, 256, 131072>>>(N, M, out);
}